// round 2
// baseline (speedup 1.0000x reference)
#include <cuda_runtime.h>
#include <math_constants.h>

#define EPSY 1e-6f
#define NB 150
#define NCLS 20
#define IOU_THR 0.5f

// 4 / pi^2
#define INV_PI2 0.405284734569351f

__device__ __forceinline__ float softplusf(float x) {
    // log(1 + exp(x)), numerically stable
    return (x > 0.0f) ? (x + log1pf(expf(-x))) : log1pf(expf(x));
}

// CIoU given fully precomputed box geometry for both boxes.
__device__ __forceinline__ float ciou_pre(
    float alx, float aly, float ahx, float ahy, float aar, float acx, float acy, float aat,
    float blx, float bly, float bhx, float bhy, float bar, float bcx, float bcy, float bat)
{
    float iw = fminf(ahx, bhx) - fmaxf(alx, blx); iw = fmaxf(iw, 0.0f);
    float ih = fminf(ahy, bhy) - fmaxf(aly, bly); ih = fmaxf(ih, 0.0f);
    float inter = iw * ih;
    float uni   = aar + bar - inter;
    float iou   = inter / fmaxf(uni, EPSY);
    float ow = fmaxf(ahx, bhx) - fminf(alx, blx);
    float oh = fmaxf(ahy, bhy) - fminf(aly, bly);
    float c2 = fmaxf(ow * ow + oh * oh, EPSY);
    float dx = acx - bcx, dy = acy - bcy;
    float u  = (dx * dx + dy * dy) / c2;
    float dv = bat - aat;
    float v  = INV_PI2 * dv * dv;
    float alpha = v / fmaxf(1.0f - iou + v, EPSY);
    return iou - (u + alpha * v);
}

__device__ __forceinline__ void box_pre(
    float x, float y, float w, float h,
    float& lx, float& ly, float& hx, float& hy, float& ar, float& at)
{
    float ltx = x - w * 0.5f, rbx = x + w * 0.5f;
    float lty = y - h * 0.5f, rby = y + h * 0.5f;
    lx = fminf(ltx, rbx); hx = fmaxf(ltx, rbx);
    ly = fminf(lty, rby); hy = fmaxf(lty, rby);
    ar = (hx - lx) * (hy - ly);
    at = atanf(w / fmaxf(h, EPSY));
}

__global__ void yolo_layer_loss_kernel(
    const float* __restrict__ p,      // (B, per_batch, 25)
    const float* __restrict__ pd,     // (B, per_batch, 25)
    const float* __restrict__ label,  // (B, per_batch, 26)
    const float* __restrict__ bb,     // (B, NB, 4)
    int per_batch,
    float inv_img2,
    float inv_bs,
    float* __restrict__ out)          // [loss, ciou, conf, cls]
{
    __shared__ float s_lx[NB], s_ly[NB], s_hx[NB], s_hy[NB];
    __shared__ float s_ar[NB], s_cx[NB], s_cy[NB], s_at[NB];
    __shared__ float s_red[3][8];

    const int b = blockIdx.y;

    for (int j = threadIdx.x; j < NB; j += blockDim.x) {
        const float* q = bb + ((size_t)b * NB + j) * 4;
        float x = q[0], y = q[1], w = q[2], h = q[3];
        float lx, ly, hx, hy, ar, at;
        box_pre(x, y, w, h, lx, ly, hx, hy, ar, at);
        s_lx[j] = lx; s_ly[j] = ly; s_hx[j] = hx; s_hy[j] = hy;
        s_ar[j] = ar; s_cx[j] = x; s_cy[j] = y; s_at[j] = at;
    }
    __syncthreads();

    const int i = blockIdx.x * blockDim.x + threadIdx.x;

    float sum_ciou = 0.0f, sum_conf = 0.0f, sum_cls = 0.0f;

    if (i < per_batch) {
        const size_t idx = (size_t)b * per_batch + i;
        const float* pdp = pd    + idx * 25;
        const float* pp  = p     + idx * 25;
        const float* lb  = label + idx * 26;

        float ax = pdp[0], ay = pdp[1], aw = pdp[2], ah = pdp[3];
        float alx, aly, ahx, ahy, aar, aat;
        box_pre(ax, ay, aw, ah, alx, aly, ahx, ahy, aar, aat);

        float lx_ = lb[0], ly_ = lb[1], lw = lb[2], lh = lb[3];
        float obj = lb[4], mix = lb[5];
        float glx, gly, ghx, ghy, gar, gat;
        box_pre(lx_, ly_, lw, lh, glx, gly, ghx, ghy, gar, gat);

        float ciou = ciou_pre(alx, aly, ahx, ahy, aar, ax, ay, aat,
                              glx, gly, ghx, ghy, gar, lx_, ly_, gat);
        float scale = 2.0f - lw * lh * inv_img2;
        sum_ciou = obj * scale * (1.0f - ciou) * mix;

        float m = -CUDART_INF_F;
        #pragma unroll 5
        for (int j = 0; j < NB; j++) {
            float c = ciou_pre(alx, aly, ahx, ahy, aar, ax, ay, aat,
                               s_lx[j], s_ly[j], s_hx[j], s_hy[j],
                               s_ar[j], s_cx[j], s_cy[j], s_at[j]);
            m = fmaxf(m, c);
        }
        float noobj = (1.0f - obj) * ((m < IOU_THR) ? 1.0f : 0.0f);

        float xc = pp[4];
        float bce = softplusf(xc) - xc * obj;
        float sg  = 1.0f / (1.0f + expf(-xc));
        float d   = obj - sg;
        float focal = bce * (d * d);   // ALPHA=1, GAMMA=2
        sum_conf = (obj + noobj) * focal * mix;

        if (obj != 0.0f) {
            float cls = 0.0f;
            #pragma unroll
            for (int c = 0; c < NCLS; c++) {
                float xcl = pp[5 + c];
                float tcl = lb[6 + c];
                cls += softplusf(xcl) - xcl * tcl;
            }
            sum_cls = obj * mix * cls;
        }
    }

    unsigned full = 0xFFFFFFFFu;
    #pragma unroll
    for (int off = 16; off > 0; off >>= 1) {
        sum_ciou += __shfl_down_sync(full, sum_ciou, off);
        sum_conf += __shfl_down_sync(full, sum_conf, off);
        sum_cls  += __shfl_down_sync(full, sum_cls,  off);
    }
    int lane = threadIdx.x & 31;
    int wid  = threadIdx.x >> 5;
    if (lane == 0) {
        s_red[0][wid] = sum_ciou;
        s_red[1][wid] = sum_conf;
        s_red[2][wid] = sum_cls;
    }
    __syncthreads();
    if (wid == 0) {
        int nw = (blockDim.x + 31) >> 5;
        float r0 = (lane < nw) ? s_red[0][lane] : 0.0f;
        float r1 = (lane < nw) ? s_red[1][lane] : 0.0f;
        float r2 = (lane < nw) ? s_red[2][lane] : 0.0f;
        #pragma unroll
        for (int off = 4; off > 0; off >>= 1) {
            r0 += __shfl_down_sync(full, r0, off);
            r1 += __shfl_down_sync(full, r1, off);
            r2 += __shfl_down_sync(full, r2, off);
        }
        if (lane == 0) {
            r0 *= inv_bs; r1 *= inv_bs; r2 *= inv_bs;
            atomicAdd(&out[1], r0);
            atomicAdd(&out[2], r1);
            atomicAdd(&out[3], r2);
            atomicAdd(&out[0], r0 + r1 + r2);
        }
    }
}

extern "C" void kernel_launch(void* const* d_in, const int* in_sizes, int n_in,
                              void* d_out, int out_size)
{
    // Robust input binding: identify tensors by element count.
    // Layer l anchor counts: B*g*g*A with B=4, A=3, grids {76,38,19}.
    //   p / p_d : n_anchors * 25  -> {1732800, 433200, 108300}
    //   label   : n_anchors * 26  -> {1802112, 450528, 112632}
    //   bboxes  : B * 150 * 4     -> 2400 (three of them, layer order 0,1,2)
    // p appears before p_d for the same layer in both plausible metadata orders.
    const int grids[3]  = { 76, 38, 19 };
    const int B = 4, A = 3;

    const float* p[3]     = { 0, 0, 0 };
    const float* pd[3]    = { 0, 0, 0 };
    const float* label[3] = { 0, 0, 0 };
    const float* bbox[3]  = { 0, 0, 0 };

    int p_size[3], l_size[3];
    for (int l = 0; l < 3; l++) {
        int na = B * grids[l] * grids[l] * A;
        p_size[l] = na * 25;
        l_size[l] = na * 26;
    }

    int bbox_seen = 0;
    for (int i = 0; i < n_in; i++) {
        int sz = in_sizes[i];
        const float* ptr = (const float*)d_in[i];
        if (sz == B * 150 * 4) {
            if (bbox_seen < 3) bbox[bbox_seen++] = ptr;
            continue;
        }
        for (int l = 0; l < 3; l++) {
            if (sz == p_size[l]) {
                if (!p[l]) p[l] = ptr; else pd[l] = ptr;
                break;
            }
            if (sz == l_size[l]) { label[l] = ptr; break; }
        }
    }

    float* out = (float*)d_out;
    cudaMemsetAsync(out, 0, 4 * sizeof(float));

    const float inv_img2 = 1.0f / (608.0f * 608.0f);  // stride*grid == 608 all layers
    const float inv_bs = 1.0f / (float)B;

    for (int l = 0; l < 3; l++) {
        int per_batch = grids[l] * grids[l] * A;
        dim3 block(256);
        dim3 grid((per_batch + 255) / 256, B);
        yolo_layer_loss_kernel<<<grid, block>>>(
            p[l], pd[l], label[l], bbox[l],
            per_batch, inv_img2, inv_bs, out);
    }
}

// round 3
// speedup vs baseline: 3.4962x; 3.4962x over previous
#include <cuda_runtime.h>
#include <math_constants.h>

#define EPSY 1e-6f
#define NB 150
#define NCLS 20
#define IOU_THR 0.5f
#define INV_PI2 0.405284734569351f   // 4/pi^2

// ---- fixed problem shape ----
#define BATCH 4
#define PB0 17328   // 76*76*3
#define PB1 4332    // 38*38*3
#define PB2 1083    // 19*19*3
#define SPLIT 4
#define APB 64              // anchors per block (256 threads / SPLIT)
#define NBLK0 271           // ceil(PB0/64)
#define NBLK1 68
#define NBLK2 17
#define CUM1 (NBLK0*BATCH)              // 1084
#define CUM2 (CUM1 + NBLK1*BATCH)       // 1356
#define TOTAL_BLOCKS (CUM2 + NBLK2*BATCH) // 1424
#define CHUNK 38            // ceil(150/4)

__device__ __forceinline__ float softplusf(float x) {
    return (x > 0.0f) ? (x + log1pf(expf(-x))) : log1pf(expf(x));
}

// CIoU with precomputed geometry; fast divides (rel_err budget is 1e-3).
__device__ __forceinline__ float ciou_pre(
    float alx, float aly, float ahx, float ahy, float aar, float acx, float acy, float aat,
    float blx, float bly, float bhx, float bhy, float bar, float bcx, float bcy, float bat)
{
    float iw = fminf(ahx, bhx) - fmaxf(alx, blx); iw = fmaxf(iw, 0.0f);
    float ih = fminf(ahy, bhy) - fmaxf(aly, bly); ih = fmaxf(ih, 0.0f);
    float inter = iw * ih;
    float uni   = aar + bar - inter;
    float iou   = __fdividef(inter, fmaxf(uni, EPSY));
    float ow = fmaxf(ahx, bhx) - fminf(alx, blx);
    float oh = fmaxf(ahy, bhy) - fminf(aly, bly);
    float c2 = fmaxf(ow * ow + oh * oh, EPSY);
    float dx = acx - bcx, dy = acy - bcy;
    float u  = __fdividef(dx * dx + dy * dy, c2);
    float dv = bat - aat;
    float v  = INV_PI2 * dv * dv;
    float alpha = __fdividef(v, fmaxf(1.0f - iou + v, EPSY));
    return iou - (u + alpha * v);
}

__device__ __forceinline__ void box_pre(
    float x, float y, float w, float h,
    float& lx, float& ly, float& hx, float& hy, float& ar, float& at)
{
    float ltx = x - w * 0.5f, rbx = x + w * 0.5f;
    float lty = y - h * 0.5f, rby = y + h * 0.5f;
    lx = fminf(ltx, rbx); hx = fmaxf(ltx, rbx);
    ly = fminf(lty, rby); hy = fmaxf(lty, rby);
    ar = (hx - lx) * (hy - ly);
    at = atanf(__fdividef(w, fmaxf(h, EPSY)));
}

__global__ __launch_bounds__(256)
void yolo_fused_kernel(
    const float* __restrict__ p0,  const float* __restrict__ p1,  const float* __restrict__ p2,
    const float* __restrict__ pd0, const float* __restrict__ pd1, const float* __restrict__ pd2,
    const float* __restrict__ lb0, const float* __restrict__ lb1, const float* __restrict__ lb2,
    const float* __restrict__ bb0, const float* __restrict__ bb1, const float* __restrict__ bb2,
    float inv_img2, float inv_bs,
    float* __restrict__ out)
{
    __shared__ float s_lx[NB], s_ly[NB], s_hx[NB], s_hy[NB];
    __shared__ float s_ar[NB], s_cx[NB], s_cy[NB], s_at[NB];
    __shared__ float s_red[3][8];

    // ---- decode block -> (layer, batch, block-within-batch) ----
    int bid = blockIdx.x;
    int layer, rem, nb, per_batch;
    const float *p, *pd, *lb, *bb;
    if (bid < CUM1)      { layer = 0; rem = bid;        nb = NBLK0; per_batch = PB0; p = p0; pd = pd0; lb = lb0; bb = bb0; }
    else if (bid < CUM2) { layer = 1; rem = bid - CUM1; nb = NBLK1; per_batch = PB1; p = p1; pd = pd1; lb = lb1; bb = bb1; }
    else                 { layer = 2; rem = bid - CUM2; nb = NBLK2; per_batch = PB2; p = p2; pd = pd2; lb = lb2; bb = bb2; }
    int b   = rem / nb;
    int blk = rem - b * nb;

    // ---- stage this batch's 150 bboxes (preprocessed) in smem ----
    for (int j = threadIdx.x; j < NB; j += blockDim.x) {
        const float* q = bb + ((size_t)b * NB + j) * 4;
        float x = q[0], y = q[1], w = q[2], h = q[3];
        float lx, ly, hx, hy, ar, at;
        box_pre(x, y, w, h, lx, ly, hx, hy, ar, at);
        s_lx[j] = lx; s_ly[j] = ly; s_hx[j] = hx; s_hy[j] = hy;
        s_ar[j] = ar; s_cx[j] = x; s_cy[j] = y; s_at[j] = at;
    }
    __syncthreads();

    const int sub = threadIdx.x & (SPLIT - 1);       // lane within anchor group
    const int i   = blk * APB + (threadIdx.x >> 2);  // anchor index within batch
    const bool valid = (i < per_batch);

    float sum_ciou = 0.0f, sum_conf = 0.0f, sum_cls = 0.0f;
    float m = -CUDART_INF_F;

    float alx, aly, ahx, ahy, aar, aat, ax, ay;
    size_t idx = 0;

    if (valid) {
        idx = (size_t)b * per_batch + i;
        const float* pdp = pd + idx * 25;
        ax = pdp[0]; ay = pdp[1];
        float aw = pdp[2], ah = pdp[3];
        box_pre(ax, ay, aw, ah, alx, aly, ahx, ahy, aar, aat);

        // each sub-lane scans its contiguous chunk of the 150 bboxes
        int j0 = sub * CHUNK;
        int j1 = min(NB, j0 + CHUNK);
        #pragma unroll 2
        for (int j = j0; j < j1; j++) {
            float c = ciou_pre(alx, aly, ahx, ahy, aar, ax, ay, aat,
                               s_lx[j], s_ly[j], s_hx[j], s_hy[j],
                               s_ar[j], s_cx[j], s_cy[j], s_at[j]);
            m = fmaxf(m, c);
        }
    }

    // combine max across the 4 sub-lanes (group-aligned, all threads participate)
    unsigned full = 0xFFFFFFFFu;
    m = fmaxf(m, __shfl_xor_sync(full, m, 1));
    m = fmaxf(m, __shfl_xor_sync(full, m, 2));

    if (valid && sub == 0) {
        const float* pp = p  + idx * 25;
        const float* lv = lb + idx * 26;

        float lx_ = lv[0], ly_ = lv[1], lw = lv[2], lh = lv[3];
        float obj = lv[4], mix = lv[5];
        float glx, gly, ghx, ghy, gar, gat;
        box_pre(lx_, ly_, lw, lh, glx, gly, ghx, ghy, gar, gat);

        float ciou = ciou_pre(alx, aly, ahx, ahy, aar, ax, ay, aat,
                              glx, gly, ghx, ghy, gar, lx_, ly_, gat);
        float scale = 2.0f - lw * lh * inv_img2;
        sum_ciou = obj * scale * (1.0f - ciou) * mix;

        float noobj = (1.0f - obj) * ((m < IOU_THR) ? 1.0f : 0.0f);

        float xc = pp[4];
        float bce = softplusf(xc) - xc * obj;
        float sg  = __fdividef(1.0f, 1.0f + expf(-xc));
        float d   = obj - sg;
        sum_conf = (obj + noobj) * (bce * d * d) * mix;   // ALPHA=1, GAMMA=2

        if (obj != 0.0f) {
            float cls = 0.0f;
            #pragma unroll
            for (int c = 0; c < NCLS; c++) {
                float xcl = pp[5 + c];
                float tcl = lv[6 + c];
                cls += softplusf(xcl) - xcl * tcl;
            }
            sum_cls = obj * mix * cls;
        }
    }

    // ---- block reduction ----
    #pragma unroll
    for (int off = 16; off > 0; off >>= 1) {
        sum_ciou += __shfl_down_sync(full, sum_ciou, off);
        sum_conf += __shfl_down_sync(full, sum_conf, off);
        sum_cls  += __shfl_down_sync(full, sum_cls,  off);
    }
    int lane = threadIdx.x & 31;
    int wid  = threadIdx.x >> 5;
    if (lane == 0) {
        s_red[0][wid] = sum_ciou;
        s_red[1][wid] = sum_conf;
        s_red[2][wid] = sum_cls;
    }
    __syncthreads();
    if (wid == 0) {
        float r0 = (lane < 8) ? s_red[0][lane] : 0.0f;
        float r1 = (lane < 8) ? s_red[1][lane] : 0.0f;
        float r2 = (lane < 8) ? s_red[2][lane] : 0.0f;
        #pragma unroll
        for (int off = 4; off > 0; off >>= 1) {
            r0 += __shfl_down_sync(full, r0, off);
            r1 += __shfl_down_sync(full, r1, off);
            r2 += __shfl_down_sync(full, r2, off);
        }
        if (lane == 0) {
            r0 *= inv_bs; r1 *= inv_bs; r2 *= inv_bs;
            atomicAdd(&out[1], r0);
            atomicAdd(&out[2], r1);
            atomicAdd(&out[3], r2);
            atomicAdd(&out[0], r0 + r1 + r2);
        }
    }
}

extern "C" void kernel_launch(void* const* d_in, const int* in_sizes, int n_in,
                              void* d_out, int out_size)
{
    // Identify tensors by element count (robust to metadata ordering).
    const int grids[3] = { 76, 38, 19 };
    const int B = 4, A = 3;

    const float* p[3]     = { 0, 0, 0 };
    const float* pd[3]    = { 0, 0, 0 };
    const float* label[3] = { 0, 0, 0 };
    const float* bbox[3]  = { 0, 0, 0 };

    int p_size[3], l_size[3];
    for (int l = 0; l < 3; l++) {
        int na = B * grids[l] * grids[l] * A;
        p_size[l] = na * 25;
        l_size[l] = na * 26;
    }

    int bbox_seen = 0;
    for (int i = 0; i < n_in; i++) {
        int sz = in_sizes[i];
        const float* ptr = (const float*)d_in[i];
        if (sz == B * 150 * 4) {
            if (bbox_seen < 3) bbox[bbox_seen++] = ptr;
            continue;
        }
        for (int l = 0; l < 3; l++) {
            if (sz == p_size[l]) {
                if (!p[l]) p[l] = ptr; else pd[l] = ptr;
                break;
            }
            if (sz == l_size[l]) { label[l] = ptr; break; }
        }
    }

    float* out = (float*)d_out;
    cudaMemsetAsync(out, 0, 4 * sizeof(float));

    const float inv_img2 = 1.0f / (608.0f * 608.0f);
    const float inv_bs = 1.0f / (float)B;

    yolo_fused_kernel<<<TOTAL_BLOCKS, 256>>>(
        p[0], p[1], p[2],
        pd[0], pd[1], pd[2],
        label[0], label[1], label[2],
        bbox[0], bbox[1], bbox[2],
        inv_img2, inv_bs, out);
}

// round 4
// speedup vs baseline: 5.4087x; 1.5470x over previous
#include <cuda_runtime.h>
#include <math_constants.h>

#define EPSY 1e-6f
#define NB 150
#define NCLS 20
#define IOU_THR 0.5f
#define INV_PI2 0.405284734569351f   // 4/pi^2

// ---- fixed problem shape ----
#define BATCH 4
#define PB0 17328   // 76*76*3
#define PB1 4332    // 38*38*3
#define PB2 1083    // 19*19*3
#define SPLIT 4
#define APB 64              // anchors per block (256 threads / SPLIT)
#define NBLK0 271
#define NBLK1 68
#define NBLK2 17
#define CUM1 (NBLK0*BATCH)               // 1084
#define CUM2 (CUM1 + NBLK1*BATCH)        // 1356
#define TOTAL_BLOCKS (CUM2 + NBLK2*BATCH) // 1424
#define CHUNK 38            // ceil(150/4)

__device__ __forceinline__ float softplusf(float x) {
    return (x > 0.0f) ? (x + log1pf(expf(-x))) : log1pf(expf(x));
}

// Full CIoU with precomputed geometry (used for label term; fast divides).
__device__ __forceinline__ float ciou_pre(
    float alx, float aly, float ahx, float ahy, float aar, float acx, float acy, float aat,
    float blx, float bly, float bhx, float bhy, float bar, float bcx, float bcy, float bat)
{
    float iw = fminf(ahx, bhx) - fmaxf(alx, blx); iw = fmaxf(iw, 0.0f);
    float ih = fminf(ahy, bhy) - fmaxf(aly, bly); ih = fmaxf(ih, 0.0f);
    float inter = iw * ih;
    float uni   = aar + bar - inter;
    float iou   = __fdividef(inter, fmaxf(uni, EPSY));
    float ow = fmaxf(ahx, bhx) - fminf(alx, blx);
    float oh = fmaxf(ahy, bhy) - fminf(aly, bly);
    float c2 = fmaxf(ow * ow + oh * oh, EPSY);
    float dx = acx - bcx, dy = acy - bcy;
    float u  = __fdividef(dx * dx + dy * dy, c2);
    float dv = bat - aat;
    float v  = INV_PI2 * dv * dv;
    float alpha = __fdividef(v, fmaxf(1.0f - iou + v, EPSY));
    return iou - (u + alpha * v);
}

__device__ __forceinline__ void box_corners(
    float x, float y, float w, float h,
    float& lx, float& ly, float& hx, float& hy, float& ar)
{
    float ltx = x - w * 0.5f, rbx = x + w * 0.5f;
    float lty = y - h * 0.5f, rby = y + h * 0.5f;
    lx = fminf(ltx, rbx); hx = fmaxf(ltx, rbx);
    ly = fminf(lty, rby); hy = fmaxf(lty, rby);
    ar = (hx - lx) * (hy - ly);
}

__global__ __launch_bounds__(256)
void yolo_fused_kernel(
    const float* __restrict__ p0,  const float* __restrict__ p1,  const float* __restrict__ p2,
    const float* __restrict__ pd0, const float* __restrict__ pd1, const float* __restrict__ pd2,
    const float* __restrict__ lb0, const float* __restrict__ lb1, const float* __restrict__ lb2,
    const float* __restrict__ bb0, const float* __restrict__ bb1, const float* __restrict__ bb2,
    float inv_img2, float inv_bs,
    float* __restrict__ out)
{
    __shared__ float4 s_geo[NB];   // lx, ly, hx, hy
    __shared__ float  s_ar[NB];    // area
    __shared__ float4 s_aux[NB];   // cx, cy, atan(w/h), unused
    __shared__ float  s_red[3][8];

    // ---- decode block -> (layer, batch, block-within-batch) ----
    int bid = blockIdx.x;
    int rem, nb, per_batch;
    const float *p, *pd, *lb, *bb;
    if (bid < CUM1)      { rem = bid;        nb = NBLK0; per_batch = PB0; p = p0; pd = pd0; lb = lb0; bb = bb0; }
    else if (bid < CUM2) { rem = bid - CUM1; nb = NBLK1; per_batch = PB1; p = p1; pd = pd1; lb = lb1; bb = bb1; }
    else                 { rem = bid - CUM2; nb = NBLK2; per_batch = PB2; p = p2; pd = pd2; lb = lb2; bb = bb2; }
    int b   = rem / nb;
    int blk = rem - b * nb;

    // ---- stage this batch's 150 bboxes (preprocessed) in smem ----
    for (int j = threadIdx.x; j < NB; j += blockDim.x) {
        const float* q = bb + ((size_t)b * NB + j) * 4;
        float x = q[0], y = q[1], w = q[2], h = q[3];
        float lx, ly, hx, hy, ar;
        box_corners(x, y, w, h, lx, ly, hx, hy, ar);
        s_geo[j] = make_float4(lx, ly, hx, hy);
        s_ar[j]  = ar;
        s_aux[j] = make_float4(x, y, atanf(__fdividef(w, fmaxf(h, EPSY))), 0.0f);
    }
    __syncthreads();

    const int sub = threadIdx.x & (SPLIT - 1);
    const int i   = blk * APB + (threadIdx.x >> 2);
    const bool valid = (i < per_batch);

    float sum_ciou = 0.0f, sum_conf = 0.0f, sum_cls = 0.0f;
    float m = -CUDART_INF_F;

    float alx, aly, ahx, ahy, aar, ax, ay, aw, ah;
    size_t idx = 0;

    if (valid) {
        idx = (size_t)b * per_batch + i;
        const float* pdp = pd + idx * 25;
        ax = pdp[0]; ay = pdp[1]; aw = pdp[2]; ah = pdp[3];
        box_corners(ax, ay, aw, ah, alx, aly, ahx, ahy, aar);

        // Fast IoU screen: CIoU <= IoU, and IoU >= 0.5  <=>  2*inter >= union.
        // Only candidates passing the screen can affect (max CIoU < 0.5),
        // and only those get the full (divides + atan) CIoU.
        int j0 = sub * CHUNK;
        int j1 = min(NB, j0 + CHUNK);
        #pragma unroll 2
        for (int j = j0; j < j1; j++) {
            float4 g = s_geo[j];
            float  br = s_ar[j];
            float iw = fminf(ahx, g.z) - fmaxf(alx, g.x); iw = fmaxf(iw, 0.0f);
            float ih = fminf(ahy, g.w) - fmaxf(aly, g.y); ih = fmaxf(ih, 0.0f);
            float inter = iw * ih;
            float uni   = aar + br - inter;
            if (2.0f * inter >= uni) {   // rare
                float4 aux = s_aux[j];
                float iou = __fdividef(inter, fmaxf(uni, EPSY));
                float ow = fmaxf(ahx, g.z) - fminf(alx, g.x);
                float oh = fmaxf(ahy, g.w) - fminf(aly, g.y);
                float c2 = fmaxf(ow * ow + oh * oh, EPSY);
                float dx = ax - aux.x, dy = ay - aux.y;
                float u  = __fdividef(dx * dx + dy * dy, c2);
                float aat = atanf(__fdividef(aw, fmaxf(ah, EPSY)));
                float dv = aux.z - aat;
                float v  = INV_PI2 * dv * dv;
                float alpha = __fdividef(v, fmaxf(1.0f - iou + v, EPSY));
                m = fmaxf(m, iou - (u + alpha * v));
            }
        }
    }

    // combine max across the 4 sub-lanes
    unsigned full = 0xFFFFFFFFu;
    m = fmaxf(m, __shfl_xor_sync(full, m, 1));
    m = fmaxf(m, __shfl_xor_sync(full, m, 2));

    if (valid && sub == 0) {
        const float* pp = p  + idx * 25;
        const float* lv = lb + idx * 26;

        float lx_ = lv[0], ly_ = lv[1], lw = lv[2], lh = lv[3];
        float obj = lv[4], mix = lv[5];
        float glx, gly, ghx, ghy, gar;
        box_corners(lx_, ly_, lw, lh, glx, gly, ghx, ghy, gar);
        float gat = atanf(__fdividef(lw, fmaxf(lh, EPSY)));
        float aat = atanf(__fdividef(aw, fmaxf(ah, EPSY)));

        float ciou = ciou_pre(alx, aly, ahx, ahy, aar, ax, ay, aat,
                              glx, gly, ghx, ghy, gar, lx_, ly_, gat);
        float scale = 2.0f - lw * lh * inv_img2;
        sum_ciou = obj * scale * (1.0f - ciou) * mix;

        float noobj = (1.0f - obj) * ((m < IOU_THR) ? 1.0f : 0.0f);

        float xc = pp[4];
        float bce = softplusf(xc) - xc * obj;
        float sg  = __fdividef(1.0f, 1.0f + expf(-xc));
        float d   = obj - sg;
        sum_conf = (obj + noobj) * (bce * d * d) * mix;   // ALPHA=1, GAMMA=2

        if (obj != 0.0f) {
            float cls = 0.0f;
            #pragma unroll
            for (int c = 0; c < NCLS; c++) {
                float xcl = pp[5 + c];
                float tcl = lv[6 + c];
                cls += softplusf(xcl) - xcl * tcl;
            }
            sum_cls = obj * mix * cls;
        }
    }

    // ---- block reduction ----
    #pragma unroll
    for (int off = 16; off > 0; off >>= 1) {
        sum_ciou += __shfl_down_sync(full, sum_ciou, off);
        sum_conf += __shfl_down_sync(full, sum_conf, off);
        sum_cls  += __shfl_down_sync(full, sum_cls,  off);
    }
    int lane = threadIdx.x & 31;
    int wid  = threadIdx.x >> 5;
    if (lane == 0) {
        s_red[0][wid] = sum_ciou;
        s_red[1][wid] = sum_conf;
        s_red[2][wid] = sum_cls;
    }
    __syncthreads();
    if (wid == 0) {
        float r0 = (lane < 8) ? s_red[0][lane] : 0.0f;
        float r1 = (lane < 8) ? s_red[1][lane] : 0.0f;
        float r2 = (lane < 8) ? s_red[2][lane] : 0.0f;
        #pragma unroll
        for (int off = 4; off > 0; off >>= 1) {
            r0 += __shfl_down_sync(full, r0, off);
            r1 += __shfl_down_sync(full, r1, off);
            r2 += __shfl_down_sync(full, r2, off);
        }
        if (lane == 0) {
            r0 *= inv_bs; r1 *= inv_bs; r2 *= inv_bs;
            atomicAdd(&out[1], r0);
            atomicAdd(&out[2], r1);
            atomicAdd(&out[3], r2);
            atomicAdd(&out[0], r0 + r1 + r2);
        }
    }
}

extern "C" void kernel_launch(void* const* d_in, const int* in_sizes, int n_in,
                              void* d_out, int out_size)
{
    // Identify tensors by element count (robust to metadata ordering).
    const int grids[3] = { 76, 38, 19 };
    const int B = 4, A = 3;

    const float* p[3]     = { 0, 0, 0 };
    const float* pd[3]    = { 0, 0, 0 };
    const float* label[3] = { 0, 0, 0 };
    const float* bbox[3]  = { 0, 0, 0 };

    int p_size[3], l_size[3];
    for (int l = 0; l < 3; l++) {
        int na = B * grids[l] * grids[l] * A;
        p_size[l] = na * 25;
        l_size[l] = na * 26;
    }

    int bbox_seen = 0;
    for (int i = 0; i < n_in; i++) {
        int sz = in_sizes[i];
        const float* ptr = (const float*)d_in[i];
        if (sz == B * 150 * 4) {
            if (bbox_seen < 3) bbox[bbox_seen++] = ptr;
            continue;
        }
        for (int l = 0; l < 3; l++) {
            if (sz == p_size[l]) {
                if (!p[l]) p[l] = ptr; else pd[l] = ptr;
                break;
            }
            if (sz == l_size[l]) { label[l] = ptr; break; }
        }
    }

    float* out = (float*)d_out;
    cudaMemsetAsync(out, 0, 4 * sizeof(float));

    const float inv_img2 = 1.0f / (608.0f * 608.0f);
    const float inv_bs = 1.0f / (float)B;

    yolo_fused_kernel<<<TOTAL_BLOCKS, 256>>>(
        p[0], p[1], p[2],
        pd[0], pd[1], pd[2],
        label[0], label[1], label[2],
        bbox[0], bbox[1], bbox[2],
        inv_img2, inv_bs, out);
}